// round 8
// baseline (speedup 1.0000x reference)
#include <cuda_runtime.h>
#include <cuda_fp16.h>
#include <cstdint>

// ---- problem constants ----
#define NPTS   25088          // 8*56*56
#define KCB    2048
#define CDIM   64
#define HW     3136           // 56*56
#define BSTRIDE 200704        // 64*3136

// output offsets (floats), tuple order: out_feat, assignment, distance, vq0_update
#define OUTF_OFF   0
#define ASSIGN_OFF 1605632
#define DIST_OFF   52985856
#define VQ_OFF     104366080

#define INVT 10.0f
#define LISTCAP 32

__device__ float  g_rowmin[NPTS];
__device__ float  g_z[NPTS];
__device__ float  g_csq[KCB];
__device__ __half g_cbH16[KCB * CDIM];   // fp16 hi part of codebook
__device__ __half g_cbL16[KCB * CDIM];   // fp16 residual lo part
__device__ int    g_cnt[NPTS];
__device__ int    g_listK[NPTS * LISTCAP];
__device__ float  g_listD[NPTS * LISTCAP];

// ---------------- K0: fp16 hi/lo codebook split + csq + zero vq ----------------
__global__ void k0_prep(const float* __restrict__ cbk, float* __restrict__ out) {
    int gid = blockIdx.x * 256 + threadIdx.x;    // 0..32767
    int code = gid >> 4, f4 = gid & 15;
    float4 v = ((const float4*)cbk)[code * 16 + f4];
    __half hx = __float2half_rn(v.x), hy = __float2half_rn(v.y);
    __half hz = __float2half_rn(v.z), hw = __float2half_rn(v.w);
    __half lx = __float2half_rn(v.x - __half2float(hx));
    __half ly = __float2half_rn(v.y - __half2float(hy));
    __half lz = __float2half_rn(v.z - __half2float(hz));
    __half lw = __float2half_rn(v.w - __half2float(hw));
    ((__half2*)g_cbH16)[code * 32 + f4 * 2]     = __halves2half2(hx, hy);
    ((__half2*)g_cbH16)[code * 32 + f4 * 2 + 1] = __halves2half2(hz, hw);
    ((__half2*)g_cbL16)[code * 32 + f4 * 2]     = __halves2half2(lx, ly);
    ((__half2*)g_cbL16)[code * 32 + f4 * 2 + 1] = __halves2half2(lz, lw);
    float p = v.x * v.x + v.y * v.y + v.z * v.z + v.w * v.w;
#pragma unroll
    for (int o = 8; o >= 1; o >>= 1) p += __shfl_xor_sync(0xffffffffu, p, o);
    if (f4 == 0) {
        g_csq[code] = p;
        out[VQ_OFF + code] = 0.0f;
    }
}

// ---------------- K1: mma.sync fp16 3-term distance GEMM + stats + sparse list ----------------
__device__ __forceinline__ void mma16816(float* c, uint32_t a0, uint32_t a1, uint32_t a2,
                                         uint32_t a3, uint32_t b0, uint32_t b1) {
    asm volatile(
        "mma.sync.aligned.m16n8k16.row.col.f32.f16.f16.f32 "
        "{%0,%1,%2,%3}, {%4,%5,%6,%7}, {%8,%9}, {%0,%1,%2,%3};"
        : "+f"(c[0]), "+f"(c[1]), "+f"(c[2]), "+f"(c[3])
        : "r"(a0), "r"(a1), "r"(a2), "r"(a3), "r"(b0), "r"(b1));
}

// smem layout (bytes)
#define PADA 68                          // floats per A row
#define SM_A    0                        // 128*68*4   = 34816
#define SM_CSQ  34816                    // 8192
#define SM_BH   43008                    // 128*36*4   = 18432
#define SM_BL   61440                    // 18432
#define K1_SMEM 79872

__global__ __launch_bounds__(256, 2) void k1_mma(const float* __restrict__ feat,
                                                 float* __restrict__ out) {
    extern __shared__ char sm[];
    float*    As   = (float*)(sm + SM_A);
    float*    csqs = (float*)(sm + SM_CSQ);
    uint32_t* Bh   = (uint32_t*)(sm + SM_BH);
    uint32_t* Bl   = (uint32_t*)(sm + SM_BL);
    __shared__ int scnt[128];

    const int t = threadIdx.x;
    const int wid = t >> 5, lane = t & 31;
    const int g = lane >> 2, t4 = lane & 3;
    const int n0 = blockIdx.x * 128;

    // stage A fp32 [row][ch] padded
#pragma unroll
    for (int i = 0; i < 32; i++) {
        int idx = t + i * 256;
        int ch = idx >> 7, row = idx & 127;
        int n = n0 + row, b = n / HW, hw = n - b * HW;
        As[row * PADA + ch] = feat[(size_t)b * BSTRIDE + (size_t)ch * HW + hw];
    }
#pragma unroll
    for (int i = 0; i < 2; i++) {
        int idx = t + i * 256;
        ((float4*)csqs)[idx] = ((const float4*)g_csq)[idx];
    }
    if (t < 128) scnt[t] = 0;
    __syncthreads();

    const int r0 = wid * 16 + g;      // rows r0 and r0+8
    float xs0 = 0.f, xs1 = 0.f;
#pragma unroll 16
    for (int c = 0; c < 64; c++) {
        float v0 = As[r0 * PADA + c], v1 = As[(r0 + 8) * PADA + c];
        xs0 = fmaf(v0, v0, xs0);
        xs1 = fmaf(v1, v1, xs1);
    }

    // resident A fragments (hi/lo), 4 k-steps
    uint32_t ah[4][4], al[4][4];
#pragma unroll
    for (int ks = 0; ks < 4; ks++) {
        int c0 = ks * 16 + 2 * t4;
#pragma unroll
        for (int p = 0; p < 4; p++) {
            int row = (p & 1) ? (r0 + 8) : r0;
            int cc = c0 + ((p >> 1) ? 8 : 0);
            float vx = As[row * PADA + cc], vy = As[row * PADA + cc + 1];
            __half hx = __float2half_rn(vx), hy = __float2half_rn(vy);
            __half2 h2 = __halves2half2(hx, hy);
            __half2 l2 = __halves2half2(__float2half_rn(vx - __half2float(hx)),
                                        __float2half_rn(vy - __half2float(hy)));
            ah[ks][p] = *(uint32_t*)&h2;
            al[ks][p] = *(uint32_t*)&l2;
        }
    }

    float m0 = __int_as_float(0x7f800000), z0 = 0.f;
    float m1 = m0, z1 = 0.f;
    int i0 = 0, i1 = 0;

    for (int ct = 0; ct < 16; ct++) {
        __syncthreads();   // protect B reuse
        // stage B tile (128 codes x 64 ch, hi+lo), rows padded to 72 halfs (144B)
#pragma unroll
        for (int i = 0; i < 4; i++) {
            int idx = t + i * 256;             // 0..1023
            int code = idx >> 3, c8 = idx & 7;
            const uint4* srcH = (const uint4*)g_cbH16 + (size_t)(ct * 128 + code) * 8 + c8;
            const uint4* srcL = (const uint4*)g_cbL16 + (size_t)(ct * 128 + code) * 8 + c8;
            *(uint4*)((char*)Bh + code * 144 + c8 * 16) = *srcH;
            *(uint4*)((char*)Bl + code * 144 + c8 * 16) = *srcL;
        }
        __syncthreads();

#pragma unroll
        for (int half = 0; half < 2; half++) {
            float acc[8][4];
#pragma unroll
            for (int j = 0; j < 8; j++)
#pragma unroll
                for (int p = 0; p < 4; p++) acc[j][p] = 0.f;

#pragma unroll
            for (int ks = 0; ks < 4; ks++) {
#pragma unroll
                for (int j = 0; j < 8; j++) {
                    int n8 = half * 8 + j;
                    int base = (n8 * 8 + g) * 36 + ks * 8 + t4;
                    uint32_t bh0 = Bh[base], bh1 = Bh[base + 4];
                    uint32_t bl0 = Bl[base], bl1 = Bl[base + 4];
                    mma16816(acc[j], ah[ks][0], ah[ks][1], ah[ks][2], ah[ks][3], bh0, bh1);
                    mma16816(acc[j], ah[ks][0], ah[ks][1], ah[ks][2], ah[ks][3], bl0, bl1);
                    mma16816(acc[j], al[ks][0], al[ks][1], al[ks][2], al[ks][3], bh0, bh1);
                }
            }

            // epilogue: distance + stats + list emit + STG.64
#pragma unroll
            for (int j = 0; j < 8; j++) {
                int col = ct * 128 + (half * 8 + j) * 8 + 2 * t4;
                float2 cs = *(float2*)&csqs[col];
                float d00 = fmaf(-2.f, acc[j][0], xs0 + cs.x);
                float d01 = fmaf(-2.f, acc[j][1], xs0 + cs.y);
                float d10 = fmaf(-2.f, acc[j][2], xs1 + cs.x);
                float d11 = fmaf(-2.f, acc[j][3], xs1 + cs.y);
                *(float2*)(out + DIST_OFF + (size_t)(n0 + r0) * KCB + col)     = make_float2(d00, d01);
                *(float2*)(out + DIST_OFF + (size_t)(n0 + r0 + 8) * KCB + col) = make_float2(d10, d11);
                if (fminf(d00, d01) < m0 + 4.0f) {
                    float thr = fminf(fminf(d00, d01), m0) + 3.3f;
                    if (d00 < thr) {
                        int pos = atomicAdd(&scnt[r0], 1);
                        if (pos < LISTCAP) {
                            g_listK[(n0 + r0) * LISTCAP + pos] = col;
                            g_listD[(n0 + r0) * LISTCAP + pos] = d00;
                        }
                    }
                    if (d01 < thr) {
                        int pos = atomicAdd(&scnt[r0], 1);
                        if (pos < LISTCAP) {
                            g_listK[(n0 + r0) * LISTCAP + pos] = col + 1;
                            g_listD[(n0 + r0) * LISTCAP + pos] = d01;
                        }
                    }
                    bool lt = d00 < m0;
                    float e = __expf((fminf(d00, m0) - fmaxf(d00, m0)) * INVT);
                    z0 = lt ? fmaf(z0, e, 1.0f) : (z0 + e);
                    i0 = lt ? col : i0;
                    m0 = fminf(m0, d00);
                    lt = d01 < m0;
                    e = __expf((fminf(d01, m0) - fmaxf(d01, m0)) * INVT);
                    z0 = lt ? fmaf(z0, e, 1.0f) : (z0 + e);
                    i0 = lt ? (col + 1) : i0;
                    m0 = fminf(m0, d01);
                }
                if (fminf(d10, d11) < m1 + 4.0f) {
                    float thr = fminf(fminf(d10, d11), m1) + 3.3f;
                    if (d10 < thr) {
                        int pos = atomicAdd(&scnt[r0 + 8], 1);
                        if (pos < LISTCAP) {
                            g_listK[(n0 + r0 + 8) * LISTCAP + pos] = col;
                            g_listD[(n0 + r0 + 8) * LISTCAP + pos] = d10;
                        }
                    }
                    if (d11 < thr) {
                        int pos = atomicAdd(&scnt[r0 + 8], 1);
                        if (pos < LISTCAP) {
                            g_listK[(n0 + r0 + 8) * LISTCAP + pos] = col + 1;
                            g_listD[(n0 + r0 + 8) * LISTCAP + pos] = d11;
                        }
                    }
                    bool lt = d10 < m1;
                    float e = __expf((fminf(d10, m1) - fmaxf(d10, m1)) * INVT);
                    z1 = lt ? fmaf(z1, e, 1.0f) : (z1 + e);
                    i1 = lt ? col : i1;
                    m1 = fminf(m1, d10);
                    lt = d11 < m1;
                    e = __expf((fminf(d11, m1) - fmaxf(d11, m1)) * INVT);
                    z1 = lt ? fmaf(z1, e, 1.0f) : (z1 + e);
                    i1 = lt ? (col + 1) : i1;
                    m1 = fminf(m1, d11);
                }
            }
        }
    }

    // reduce (m,z,argmin) over the 4-lane quad (same rows)
#pragma unroll
    for (int o = 1; o <= 2; o <<= 1) {
        float m2 = __shfl_xor_sync(0xffffffffu, m0, o);
        float z2 = __shfl_xor_sync(0xffffffffu, z0, o);
        int   j2 = __shfl_xor_sync(0xffffffffu, i0, o);
        float mn = fminf(m0, m2);
        z0 = z0 * __expf((mn - m0) * INVT) + z2 * __expf((mn - m2) * INVT);
        i0 = (m2 < m0) ? j2 : i0;
        m0 = mn;
        m2 = __shfl_xor_sync(0xffffffffu, m1, o);
        z2 = __shfl_xor_sync(0xffffffffu, z1, o);
        j2 = __shfl_xor_sync(0xffffffffu, i1, o);
        mn = fminf(m1, m2);
        z1 = z1 * __expf((mn - m1) * INVT) + z2 * __expf((mn - m2) * INVT);
        i1 = (m2 < m1) ? j2 : i1;
        m1 = mn;
    }
    if (t4 == 0) {
        g_rowmin[n0 + r0] = m0;  g_z[n0 + r0] = z0;
        atomicAdd(out + VQ_OFF + i0, 1.0f);
        g_rowmin[n0 + r0 + 8] = m1;  g_z[n0 + r0 + 8] = z1;
        atomicAdd(out + VQ_OFF + i1, 1.0f);
    }
    __syncthreads();
    if (t < 128) g_cnt[n0 + t] = scnt[t];
}

// ---------------- K2z: zero-fill assignment (pure stream writes) ----------------
// 12544 CTAs x 256 threads x 4 float4 = 51380224 floats exactly.
__global__ void k2_zero(float* __restrict__ out) {
    size_t base = (size_t)blockIdx.x * 1024 + threadIdx.x;
    float4 z = make_float4(0.f, 0.f, 0.f, 0.f);
    float4* dst = (float4*)(out + ASSIGN_OFF);
#pragma unroll
    for (int j = 0; j < 4; j++) dst[base + j * 256] = z;
}

// ---------------- K3: scatter sparse probs + q_feat/out_feat ----------------
// 3136 CTAs x 256 threads; warp per row (8 rows/CTA, same batch, consecutive hw).
__global__ __launch_bounds__(256) void k3_scatter(const float* __restrict__ cbk,
                                                  float* __restrict__ out) {
    __shared__ float sqf[8][65];
    const int t = threadIdx.x, wid = t >> 5, lane = t & 31;
    const int n0 = blockIdx.x * 8;
    const int b = n0 / HW, hw0 = n0 % HW;
    const int n = n0 + wid, hw = hw0 + wid;

    const float m = g_rowmin[n];
    const float zi = __frcp_rn(g_z[n]);
    const int cnt = g_cnt[n];
    float* assign = out + ASSIGN_OFF + (size_t)b * (KCB * HW) + hw;

    float qf0 = 0.f, qf1 = 0.f;
    if (cnt <= LISTCAP) {
        int k = 0;
        float p = 0.f;
        if (lane < cnt) {
            k = g_listK[n * LISTCAP + lane];
            float d = g_listD[n * LISTCAP + lane];
            float arg = (m - d) * INVT;
            p = (arg > -60.f) ? __expf(arg) * zi : 0.f;
            assign[(size_t)k * HW] = p;
        }
        for (int e = 0; e < cnt; e++) {
            float pe = __shfl_sync(0xffffffffu, p, e);
            int   ke = __shfl_sync(0xffffffffu, k, e);
            if (pe > 1e-12f) {
                qf0 = fmaf(pe, cbk[ke * 64 + lane], qf0);
                qf1 = fmaf(pe, cbk[ke * 64 + 32 + lane], qf1);
            }
        }
    } else {
        // rare fallback: dense scan of this row's distances
        const float* dist = out + DIST_OFF + (size_t)n * KCB;
        for (int c0 = 0; c0 < 64; c0++) {
            int kk = c0 * 32 + lane;
            float d = dist[kk];
            float arg = (m - d) * INVT;
            float p = (arg > -60.f) ? __expf(arg) * zi : 0.f;
            assign[(size_t)kk * HW] = p;
            unsigned mask = __ballot_sync(0xffffffffu, p > 1e-12f);
            while (mask) {
                int src = __ffs(mask) - 1;
                mask &= mask - 1;
                float pe = __shfl_sync(0xffffffffu, p, src);
                int   ke = __shfl_sync(0xffffffffu, kk, src);
                qf0 = fmaf(pe, cbk[ke * 64 + lane], qf0);
                qf1 = fmaf(pe, cbk[ke * 64 + 32 + lane], qf1);
            }
        }
    }
    sqf[wid][lane] = qf0;
    sqf[wid][32 + lane] = qf1;
    __syncthreads();

    // out_feat (c,hw) for 8 rows
    float* of = out + OUTF_OFF + (size_t)b * BSTRIDE + hw0;
#pragma unroll
    for (int i = 0; i < 2; i++) {
        int idx = t + i * 256;           // 0..511
        int ch = idx >> 3, r = idx & 7;
        of[(size_t)ch * HW + r] = sqf[r][ch];
    }
}

extern "C" void kernel_launch(void* const* d_in, const int* in_sizes, int n_in,
                              void* d_out, int out_size) {
    const float* feat = (const float*)d_in[0];
    const float* cbk  = (const float*)d_in[1];
    float* out = (float*)d_out;

    cudaFuncSetAttribute(k1_mma, cudaFuncAttributeMaxDynamicSharedMemorySize, K1_SMEM);

    k0_prep<<<128, 256>>>(cbk, out);
    k2_zero<<<12544, 256>>>(out);
    k1_mma<<<NPTS / 128, 256, K1_SMEM>>>(feat, out);
    k3_scatter<<<NPTS / 8, 256>>>(cbk, out);
}

// round 9
// speedup vs baseline: 2.8605x; 2.8605x over previous
#include <cuda_runtime.h>
#include <cuda_fp16.h>
#include <cstdint>

// ---- problem constants ----
#define NPTS   25088          // 8*56*56
#define KCB    2048
#define CDIM   64
#define HW     3136           // 56*56
#define BSTRIDE 200704        // 64*3136

// output offsets (floats), tuple order: out_feat, assignment, distance, vq0_update
#define OUTF_OFF   0
#define ASSIGN_OFF 1605632
#define DIST_OFF   52985856
#define VQ_OFF     104366080

#define INVT 10.0f
#define LISTCAP 64

__device__ float  g_rowmin[NPTS];
__device__ float  g_z[NPTS];
__device__ float  g_csq[KCB];
__device__ __half g_cbH16[KCB * CDIM];   // fp16 hi part of codebook
__device__ __half g_cbL16[KCB * CDIM];   // fp16 residual lo part
__device__ int    g_cnt[NPTS];
__device__ int    g_listK[NPTS * LISTCAP];
__device__ float  g_listD[NPTS * LISTCAP];

// ---------------- K0: fp16 hi/lo codebook split + csq + zero vq ----------------
__global__ void k0_prep(const float* __restrict__ cbk, float* __restrict__ out) {
    int gid = blockIdx.x * 256 + threadIdx.x;    // 0..32767
    int code = gid >> 4, f4 = gid & 15;
    float4 v = ((const float4*)cbk)[code * 16 + f4];
    __half hx = __float2half_rn(v.x), hy = __float2half_rn(v.y);
    __half hz = __float2half_rn(v.z), hw = __float2half_rn(v.w);
    __half lx = __float2half_rn(v.x - __half2float(hx));
    __half ly = __float2half_rn(v.y - __half2float(hy));
    __half lz = __float2half_rn(v.z - __half2float(hz));
    __half lw = __float2half_rn(v.w - __half2float(hw));
    ((__half2*)g_cbH16)[code * 32 + f4 * 2]     = __halves2half2(hx, hy);
    ((__half2*)g_cbH16)[code * 32 + f4 * 2 + 1] = __halves2half2(hz, hw);
    ((__half2*)g_cbL16)[code * 32 + f4 * 2]     = __halves2half2(lx, ly);
    ((__half2*)g_cbL16)[code * 32 + f4 * 2 + 1] = __halves2half2(lz, lw);
    float p = v.x * v.x + v.y * v.y + v.z * v.z + v.w * v.w;
#pragma unroll
    for (int o = 8; o >= 1; o >>= 1) p += __shfl_xor_sync(0xffffffffu, p, o);
    if (f4 == 0) {
        g_csq[code] = p;
        out[VQ_OFF + code] = 0.0f;
    }
}

// ---------------- K1: mma.sync fp16 3-term distance GEMM + stats + sparse list ----------------
__device__ __forceinline__ void mma16816(float* c, uint32_t a0, uint32_t a1, uint32_t a2,
                                         uint32_t a3, uint32_t b0, uint32_t b1) {
    asm volatile(
        "mma.sync.aligned.m16n8k16.row.col.f32.f16.f16.f32 "
        "{%0,%1,%2,%3}, {%4,%5,%6,%7}, {%8,%9}, {%0,%1,%2,%3};"
        : "+f"(c[0]), "+f"(c[1]), "+f"(c[2]), "+f"(c[3])
        : "r"(a0), "r"(a1), "r"(a2), "r"(a3), "r"(b0), "r"(b1));
}

// smem layout (bytes)
#define PADA 68                          // floats per A row
#define SM_A    0                        // 128*68*4   = 34816
#define SM_CSQ  34816                    // 8192
#define SM_BH   43008                    // 128*36*4   = 18432
#define SM_BL   61440                    // 18432
#define K1_SMEM 79872

__global__ __launch_bounds__(256, 2) void k1_mma(const float* __restrict__ feat,
                                                 float* __restrict__ out) {
    extern __shared__ char sm[];
    float*    As   = (float*)(sm + SM_A);
    float*    csqs = (float*)(sm + SM_CSQ);
    uint32_t* Bh   = (uint32_t*)(sm + SM_BH);
    uint32_t* Bl   = (uint32_t*)(sm + SM_BL);
    __shared__ int scnt[128];

    const int t = threadIdx.x;
    const int wid = t >> 5, lane = t & 31;
    const int g = lane >> 2, t4 = lane & 3;
    const int n0 = blockIdx.x * 128;

    // stage A fp32 [row][ch] padded
#pragma unroll
    for (int i = 0; i < 32; i++) {
        int idx = t + i * 256;
        int ch = idx >> 7, row = idx & 127;
        int n = n0 + row, b = n / HW, hw = n - b * HW;
        As[row * PADA + ch] = feat[(size_t)b * BSTRIDE + (size_t)ch * HW + hw];
    }
#pragma unroll
    for (int i = 0; i < 2; i++) {
        int idx = t + i * 256;
        ((float4*)csqs)[idx] = ((const float4*)g_csq)[idx];
    }
    if (t < 128) scnt[t] = 0;
    __syncthreads();

    const int r0 = wid * 16 + g;      // rows r0 and r0+8
    float xs0 = 0.f, xs1 = 0.f;
#pragma unroll 16
    for (int c = 0; c < 64; c++) {
        float v0 = As[r0 * PADA + c], v1 = As[(r0 + 8) * PADA + c];
        xs0 = fmaf(v0, v0, xs0);
        xs1 = fmaf(v1, v1, xs1);
    }

    // resident A fragments (hi/lo), 4 k-steps
    uint32_t ah[4][4], al[4][4];
#pragma unroll
    for (int ks = 0; ks < 4; ks++) {
        int c0 = ks * 16 + 2 * t4;
#pragma unroll
        for (int p = 0; p < 4; p++) {
            int row = (p & 1) ? (r0 + 8) : r0;
            int cc = c0 + ((p >> 1) ? 8 : 0);
            float vx = As[row * PADA + cc], vy = As[row * PADA + cc + 1];
            __half hx = __float2half_rn(vx), hy = __float2half_rn(vy);
            __half2 h2 = __halves2half2(hx, hy);
            __half2 l2 = __halves2half2(__float2half_rn(vx - __half2float(hx)),
                                        __float2half_rn(vy - __half2float(hy)));
            ah[ks][p] = *(uint32_t*)&h2;
            al[ks][p] = *(uint32_t*)&l2;
        }
    }

    float m0 = __int_as_float(0x7f800000), z0 = 0.f;
    float m1 = m0, z1 = 0.f;
    int i0 = 0, i1 = 0;
    float mshare0 = m0, mshare1 = m0;   // quad-shared running row mins (emission only)

    for (int ct = 0; ct < 16; ct++) {
        __syncthreads();   // protect B reuse
        // stage B tile (128 codes x 64 ch, hi+lo), rows padded to 72 halfs (144B)
#pragma unroll
        for (int i = 0; i < 4; i++) {
            int idx = t + i * 256;             // 0..1023
            int code = idx >> 3, c8 = idx & 7;
            const uint4* srcH = (const uint4*)g_cbH16 + (size_t)(ct * 128 + code) * 8 + c8;
            const uint4* srcL = (const uint4*)g_cbL16 + (size_t)(ct * 128 + code) * 8 + c8;
            *(uint4*)((char*)Bh + code * 144 + c8 * 16) = *srcH;
            *(uint4*)((char*)Bl + code * 144 + c8 * 16) = *srcL;
        }
        __syncthreads();

#pragma unroll
        for (int half = 0; half < 2; half++) {
            float acc[8][4];
#pragma unroll
            for (int j = 0; j < 8; j++)
#pragma unroll
                for (int p = 0; p < 4; p++) acc[j][p] = 0.f;

#pragma unroll
            for (int ks = 0; ks < 4; ks++) {
#pragma unroll
                for (int j = 0; j < 8; j++) {
                    int n8 = half * 8 + j;
                    int base = (n8 * 8 + g) * 36 + ks * 8 + t4;
                    uint32_t bh0 = Bh[base], bh1 = Bh[base + 4];
                    uint32_t bl0 = Bl[base], bl1 = Bl[base + 4];
                    mma16816(acc[j], ah[ks][0], ah[ks][1], ah[ks][2], ah[ks][3], bh0, bh1);
                    mma16816(acc[j], ah[ks][0], ah[ks][1], ah[ks][2], ah[ks][3], bl0, bl1);
                    mma16816(acc[j], al[ks][0], al[ks][1], al[ks][2], al[ks][3], bh0, bh1);
                }
            }

            // epilogue: distance + stats + list emit + STG.64
#pragma unroll
            for (int j = 0; j < 8; j++) {
                int col = ct * 128 + (half * 8 + j) * 8 + 2 * t4;
                float2 cs = *(float2*)&csqs[col];
                float d00 = fmaf(-2.f, acc[j][0], xs0 + cs.x);
                float d01 = fmaf(-2.f, acc[j][1], xs0 + cs.y);
                float d10 = fmaf(-2.f, acc[j][2], xs1 + cs.x);
                float d11 = fmaf(-2.f, acc[j][3], xs1 + cs.y);
                *(float2*)(out + DIST_OFF + (size_t)(n0 + r0) * KCB + col)     = make_float2(d00, d01);
                *(float2*)(out + DIST_OFF + (size_t)(n0 + r0 + 8) * KCB + col) = make_float2(d10, d11);
                float pmin0 = fminf(d00, d01);
                float base0 = fminf(mshare0, m0);
                if (pmin0 < base0 + 3.3f) {
                    float thr = fminf(base0, pmin0) + 3.3f;
                    if (d00 < thr) {
                        int pos = atomicAdd(&scnt[r0], 1);
                        if (pos < LISTCAP) {
                            g_listK[(n0 + r0) * LISTCAP + pos] = col;
                            g_listD[(n0 + r0) * LISTCAP + pos] = d00;
                        }
                    }
                    if (d01 < thr) {
                        int pos = atomicAdd(&scnt[r0], 1);
                        if (pos < LISTCAP) {
                            g_listK[(n0 + r0) * LISTCAP + pos] = col + 1;
                            g_listD[(n0 + r0) * LISTCAP + pos] = d01;
                        }
                    }
                }
                if (pmin0 < m0 + 4.0f) {
                    bool lt = d00 < m0;
                    float e = __expf((fminf(d00, m0) - fmaxf(d00, m0)) * INVT);
                    z0 = lt ? fmaf(z0, e, 1.0f) : (z0 + e);
                    i0 = lt ? col : i0;
                    m0 = fminf(m0, d00);
                    lt = d01 < m0;
                    e = __expf((fminf(d01, m0) - fmaxf(d01, m0)) * INVT);
                    z0 = lt ? fmaf(z0, e, 1.0f) : (z0 + e);
                    i0 = lt ? (col + 1) : i0;
                    m0 = fminf(m0, d01);
                }
                float pmin1 = fminf(d10, d11);
                float base1 = fminf(mshare1, m1);
                if (pmin1 < base1 + 3.3f) {
                    float thr = fminf(base1, pmin1) + 3.3f;
                    if (d10 < thr) {
                        int pos = atomicAdd(&scnt[r0 + 8], 1);
                        if (pos < LISTCAP) {
                            g_listK[(n0 + r0 + 8) * LISTCAP + pos] = col;
                            g_listD[(n0 + r0 + 8) * LISTCAP + pos] = d10;
                        }
                    }
                    if (d11 < thr) {
                        int pos = atomicAdd(&scnt[r0 + 8], 1);
                        if (pos < LISTCAP) {
                            g_listK[(n0 + r0 + 8) * LISTCAP + pos] = col + 1;
                            g_listD[(n0 + r0 + 8) * LISTCAP + pos] = d11;
                        }
                    }
                }
                if (pmin1 < m1 + 4.0f) {
                    bool lt = d10 < m1;
                    float e = __expf((fminf(d10, m1) - fmaxf(d10, m1)) * INVT);
                    z1 = lt ? fmaf(z1, e, 1.0f) : (z1 + e);
                    i1 = lt ? col : i1;
                    m1 = fminf(m1, d10);
                    lt = d11 < m1;
                    e = __expf((fminf(d11, m1) - fmaxf(d11, m1)) * INVT);
                    z1 = lt ? fmaf(z1, e, 1.0f) : (z1 + e);
                    i1 = lt ? (col + 1) : i1;
                    m1 = fminf(m1, d11);
                }
            }
        }
        // sync shared running mins across the quad (emission threshold only)
        {
            float v0 = fminf(mshare0, m0);
            v0 = fminf(v0, __shfl_xor_sync(0xffffffffu, v0, 1));
            v0 = fminf(v0, __shfl_xor_sync(0xffffffffu, v0, 2));
            mshare0 = v0;
            float v1 = fminf(mshare1, m1);
            v1 = fminf(v1, __shfl_xor_sync(0xffffffffu, v1, 1));
            v1 = fminf(v1, __shfl_xor_sync(0xffffffffu, v1, 2));
            mshare1 = v1;
        }
    }

    // reduce (m,z,argmin) over the 4-lane quad (same rows)
#pragma unroll
    for (int o = 1; o <= 2; o <<= 1) {
        float m2 = __shfl_xor_sync(0xffffffffu, m0, o);
        float z2 = __shfl_xor_sync(0xffffffffu, z0, o);
        int   j2 = __shfl_xor_sync(0xffffffffu, i0, o);
        float mn = fminf(m0, m2);
        z0 = z0 * __expf((mn - m0) * INVT) + z2 * __expf((mn - m2) * INVT);
        i0 = (m2 < m0) ? j2 : i0;
        m0 = mn;
        m2 = __shfl_xor_sync(0xffffffffu, m1, o);
        z2 = __shfl_xor_sync(0xffffffffu, z1, o);
        j2 = __shfl_xor_sync(0xffffffffu, i1, o);
        mn = fminf(m1, m2);
        z1 = z1 * __expf((mn - m1) * INVT) + z2 * __expf((mn - m2) * INVT);
        i1 = (m2 < m1) ? j2 : i1;
        m1 = mn;
    }
    if (t4 == 0) {
        g_rowmin[n0 + r0] = m0;  g_z[n0 + r0] = z0;
        atomicAdd(out + VQ_OFF + i0, 1.0f);
        g_rowmin[n0 + r0 + 8] = m1;  g_z[n0 + r0 + 8] = z1;
        atomicAdd(out + VQ_OFF + i1, 1.0f);
    }
    __syncthreads();
    if (t < 128) g_cnt[n0 + t] = scnt[t];
}

// ---------------- K2z: zero-fill assignment (pure stream writes) ----------------
__global__ void k2_zero(float* __restrict__ out) {
    size_t base = (size_t)blockIdx.x * 1024 + threadIdx.x;
    float4 z = make_float4(0.f, 0.f, 0.f, 0.f);
    float4* dst = (float4*)(out + ASSIGN_OFF);
#pragma unroll
    for (int j = 0; j < 4; j++) dst[base + j * 256] = z;
}

// ---------------- K3: scatter sparse probs + q_feat/out_feat ----------------
// 3136 CTAs x 256 threads; warp per row (8 rows/CTA, same batch, consecutive hw).
__global__ __launch_bounds__(256) void k3_scatter(const float* __restrict__ cbk,
                                                  float* __restrict__ out) {
    __shared__ float sqf[8][65];
    const int t = threadIdx.x, wid = t >> 5, lane = t & 31;
    const int n0 = blockIdx.x * 8;
    const int b = n0 / HW, hw0 = n0 % HW;
    const int n = n0 + wid, hw = hw0 + wid;

    const float m = g_rowmin[n];
    const float zi = __frcp_rn(g_z[n]);
    const int cnt = g_cnt[n];
    float* assign = out + ASSIGN_OFF + (size_t)b * (KCB * HW) + hw;

    float qf0 = 0.f, qf1 = 0.f;
    if (cnt <= LISTCAP) {
        int ka = 0, kb = 0;
        float pa = 0.f, pb = 0.f;
        if (lane < cnt) {
            ka = g_listK[n * LISTCAP + lane];
            float d = g_listD[n * LISTCAP + lane];
            float arg = (m - d) * INVT;
            pa = (arg > -60.f) ? __expf(arg) * zi : 0.f;
            assign[(size_t)ka * HW] = pa;
        }
        if (32 + lane < cnt) {
            kb = g_listK[n * LISTCAP + 32 + lane];
            float d = g_listD[n * LISTCAP + 32 + lane];
            float arg = (m - d) * INVT;
            pb = (arg > -60.f) ? __expf(arg) * zi : 0.f;
            assign[(size_t)kb * HW] = pb;
        }
        for (int e = 0; e < cnt; e++) {
            float pe = (e < 32) ? __shfl_sync(0xffffffffu, pa, e)
                                : __shfl_sync(0xffffffffu, pb, e - 32);
            int   ke = (e < 32) ? __shfl_sync(0xffffffffu, ka, e)
                                : __shfl_sync(0xffffffffu, kb, e - 32);
            if (pe > 1e-12f) {
                qf0 = fmaf(pe, cbk[ke * 64 + lane], qf0);
                qf1 = fmaf(pe, cbk[ke * 64 + 32 + lane], qf1);
            }
        }
    } else {
        // rare fallback: dense scan of this row's distances
        const float* dist = out + DIST_OFF + (size_t)n * KCB;
        for (int c0 = 0; c0 < 64; c0++) {
            int kk = c0 * 32 + lane;
            float d = dist[kk];
            float arg = (m - d) * INVT;
            float p = (arg > -60.f) ? __expf(arg) * zi : 0.f;
            assign[(size_t)kk * HW] = p;
            unsigned mask = __ballot_sync(0xffffffffu, p > 1e-12f);
            while (mask) {
                int src = __ffs(mask) - 1;
                mask &= mask - 1;
                float pe = __shfl_sync(0xffffffffu, p, src);
                int   ke = __shfl_sync(0xffffffffu, kk, src);
                qf0 = fmaf(pe, cbk[ke * 64 + lane], qf0);
                qf1 = fmaf(pe, cbk[ke * 64 + 32 + lane], qf1);
            }
        }
    }
    sqf[wid][lane] = qf0;
    sqf[wid][32 + lane] = qf1;
    __syncthreads();

    // out_feat (c,hw) for 8 rows
    float* of = out + OUTF_OFF + (size_t)b * BSTRIDE + hw0;
#pragma unroll
    for (int i = 0; i < 2; i++) {
        int idx = t + i * 256;           // 0..511
        int ch = idx >> 3, r = idx & 7;
        of[(size_t)ch * HW + r] = sqf[r][ch];
    }
}

extern "C" void kernel_launch(void* const* d_in, const int* in_sizes, int n_in,
                              void* d_out, int out_size) {
    const float* feat = (const float*)d_in[0];
    const float* cbk  = (const float*)d_in[1];
    float* out = (float*)d_out;

    cudaFuncSetAttribute(k1_mma, cudaFuncAttributeMaxDynamicSharedMemorySize, K1_SMEM);

    k0_prep<<<128, 256>>>(cbk, out);
    k2_zero<<<12544, 256>>>(out);
    k1_mma<<<NPTS / 128, 256, K1_SMEM>>>(feat, out);
    k3_scatter<<<NPTS / 8, 256>>>(cbk, out);
}